// round 1
// baseline (speedup 1.0000x reference)
#include <cuda_runtime.h>
#include <math.h>

// Problem constants (fixed by the reference)
#define NS      65536
#define NBUS    32
#define HD      256
#define TM      16          // samples per CTA
#define THREADS 256

// d_out layout: [out | out_t | physics], each [NS, NBUS] float32, concatenated.

__global__ void __launch_bounds__(THREADS, 1) pinn_kernel(
    const float* __restrict__ t_in,     // [NS,1]
    const float* __restrict__ power,    // [NS,NBUS]
    const float* __restrict__ W0,       // [1,HD]
    const float* __restrict__ b0,       // [HD]
    const float* __restrict__ W1,       // [HD,HD]
    const float* __restrict__ b1,       // [HD]
    const float* __restrict__ W2,       // [HD,NBUS]
    const float* __restrict__ b2,       // [NBUS]
    const float* __restrict__ lam_m,    // [NBUS]
    const float* __restrict__ lam_d,    // [NBUS]
    const float* __restrict__ lam_b,    // [NBUS,NBUS]
    const float* __restrict__ bwi,      // [NBUS]
    float* __restrict__ out_d,          // [NS,NBUS]
    float* __restrict__ out_dt,         // [NS,NBUS]
    float* __restrict__ out_ph)         // [NS,NBUS]
{
    // 3 * 256 * 16 floats = 49152 bytes (exactly the 48KB static limit).
    __shared__ __align__(16) float sh[3 * HD * TM];
    float* sh_h = sh;                 // [HD][TM] transposed: value / d/dt / d2/dt2
    float* sh_p = sh + HD * TM;
    float* sh_q = sh + 2 * HD * TM;

    const int tid  = threadIdx.x;
    const int base = blockIdx.x * TM;

    // ---------------- Phase A: layer 0 + its t-derivatives -------------------
    // x = 2t/20 - 1 = 0.1t - 1 ; dx/dt = 0.1 ; d2x/dt2 = 0
    // h = tanh(x*W0k + b0k); h' = (1-h^2)*(0.1*W0k); h'' = -2 h (1-h^2) (0.1*W0k)^2
    #pragma unroll
    for (int idx = tid; idx < HD * TM; idx += THREADS) {
        const int k = idx >> 4;
        const int m = idx & (TM - 1);
        const float t = __ldg(&t_in[base + m]);
        const float x = fmaf(t, 0.1f, -1.0f);
        const float w = __ldg(&W0[k]);
        const float z = fmaf(x, w, __ldg(&b0[k]));
        const float h = tanhf(z);
        const float u = 1.0f - h * h;
        const float d = 0.1f * w;
        sh_h[idx] = h;
        sh_p[idx] = u * d;
        sh_q[idx] = -2.0f * h * u * d * d;
    }
    __syncthreads();

    // ---------------- Phase B: fused 3-stream GEMM with W1 --------------------
    // Thread tid owns output column j = tid. One pass over W1 feeds all 3
    // derivative streams (48 FFMA per LDG; W1 read once per CTA).
    float a0[TM], a1[TM], a2[TM];
    {
        const float bj = __ldg(&b1[tid]);
        #pragma unroll
        for (int m = 0; m < TM; m++) { a0[m] = bj; a1[m] = 0.0f; a2[m] = 0.0f; }
    }
    const float* w1col = W1 + tid;
    float wv = __ldg(w1col);                      // prefetch k = 0
    for (int k = 0; k < HD; k++) {
        const float wn = (k + 1 < HD) ? __ldg(w1col + (k + 1) * HD) : 0.0f;
        const float4* h4 = (const float4*)(sh_h + (k << 4));
        const float4* p4 = (const float4*)(sh_p + (k << 4));
        const float4* q4 = (const float4*)(sh_q + (k << 4));
        #pragma unroll
        for (int v = 0; v < TM / 4; v++) {
            const float4 hv = h4[v];
            const float4 pv = p4[v];
            const float4 qv = q4[v];
            a0[4*v+0] = fmaf(hv.x, wv, a0[4*v+0]);
            a0[4*v+1] = fmaf(hv.y, wv, a0[4*v+1]);
            a0[4*v+2] = fmaf(hv.z, wv, a0[4*v+2]);
            a0[4*v+3] = fmaf(hv.w, wv, a0[4*v+3]);
            a1[4*v+0] = fmaf(pv.x, wv, a1[4*v+0]);
            a1[4*v+1] = fmaf(pv.y, wv, a1[4*v+1]);
            a1[4*v+2] = fmaf(pv.z, wv, a1[4*v+2]);
            a1[4*v+3] = fmaf(pv.w, wv, a1[4*v+3]);
            a2[4*v+0] = fmaf(qv.x, wv, a2[4*v+0]);
            a2[4*v+1] = fmaf(qv.y, wv, a2[4*v+1]);
            a2[4*v+2] = fmaf(qv.z, wv, a2[4*v+2]);
            a2[4*v+3] = fmaf(qv.w, wv, a2[4*v+3]);
        }
        wv = wn;
    }
    __syncthreads();   // everyone done READING sh_h/p/q before overwrite

    // ---------------- Phase C: layer-1 tanh chain -----------------------------
    // g = tanh(z); g' = (1-g^2) z'; g'' = (1-g^2)(z'' - 2 g z'^2)
    #pragma unroll
    for (int m = 0; m < TM; m++) {
        const float g  = tanhf(a0[m]);
        const float u  = 1.0f - g * g;
        const float zp = a1[m];
        sh_h[tid * TM + m] = g;
        sh_p[tid * TM + m] = u * zp;
        sh_q[tid * TM + m] = u * (a2[m] - 2.0f * g * zp * zp);
    }
    __syncthreads();

    // ---------------- Phase D: 256 -> 32 projection ---------------------------
    // Thread layout: i = tid%32 (bus, coalesced), mq = tid/32; 2 samples each.
    const int i  = tid & 31;
    const int mq = tid >> 5;
    float o[2], op[2], opp[2];
    {
        const float bb = __ldg(&b2[i]);
        o[0] = bb; o[1] = bb;
        op[0] = 0.0f; op[1] = 0.0f;
        opp[0] = 0.0f; opp[1] = 0.0f;
    }
    for (int j = 0; j < HD; j++) {
        const float w2 = __ldg(&W2[j * NBUS + i]);
        #pragma unroll
        for (int s = 0; s < 2; s++) {
            const int m = mq + 8 * s;
            o[s]   = fmaf(sh_h[j * TM + m], w2, o[s]);
            op[s]  = fmaf(sh_p[j * TM + m], w2, op[s]);
            opp[s] = fmaf(sh_q[j * TM + m], w2, opp[s]);
        }
    }
    __syncthreads();   // done reading g/g'/g'' ; reuse smem for sin/cos

    // ---------------- Phase E: coupling + physics -----------------------------
    // sum_j B[i][j] sin(d_i - d_j) = s_i*(B@c)_i - c_i*(B@s)_i
    float* sh_s = sh;                 // [TM][NBUS]
    float* sh_c = sh + TM * NBUS;     // [TM][NBUS]
    float sv[2], cv[2];
    #pragma unroll
    for (int s = 0; s < 2; s++) {
        const int m = mq + 8 * s;
        sincosf(o[s], &sv[s], &cv[s]);
        sh_s[m * NBUS + i] = sv[s];
        sh_c[m * NBUS + i] = cv[s];
    }
    __syncthreads();

    const float lm = __ldg(&lam_m[i]) * __ldg(&bwi[i]);
    const float ld = __ldg(&lam_d[i]);
    #pragma unroll
    for (int s = 0; s < 2; s++) {
        const int m = mq + 8 * s;
        float accC = 0.0f, accS = 0.0f;
        #pragma unroll
        for (int j = 0; j < NBUS; j++) {
            const float bij = __ldg(&lam_b[i * NBUS + j]);
            accC = fmaf(bij, sh_c[m * NBUS + j], accC);
            accS = fmaf(bij, sh_s[m * NBUS + j], accS);
        }
        const float conn = sv[s] * accC - cv[s] * accS;
        const int gi = (base + m) * NBUS + i;
        const float ph = fmaf(lm, opp[s], fmaf(ld, op[s], conn - __ldg(&power[gi])));
        out_d[gi]  = o[s];
        out_dt[gi] = op[s];
        out_ph[gi] = ph;
    }
}

extern "C" void kernel_launch(void* const* d_in, const int* in_sizes, int n_in,
                              void* d_out, int out_size) {
    const float* t_in  = (const float*)d_in[0];
    const float* power = (const float*)d_in[1];
    const float* W0    = (const float*)d_in[2];
    const float* b0    = (const float*)d_in[3];
    const float* W1    = (const float*)d_in[4];
    const float* b1    = (const float*)d_in[5];
    const float* W2    = (const float*)d_in[6];
    const float* b2    = (const float*)d_in[7];
    const float* lam_m = (const float*)d_in[8];
    const float* lam_d = (const float*)d_in[9];
    const float* lam_b = (const float*)d_in[10];
    const float* bwi   = (const float*)d_in[11];

    float* out  = (float*)d_out;
    float* outt = out  + (size_t)NS * NBUS;
    float* outp = outt + (size_t)NS * NBUS;

    pinn_kernel<<<NS / TM, THREADS>>>(t_in, power, W0, b0, W1, b1, W2, b2,
                                      lam_m, lam_d, lam_b, bwi,
                                      out, outt, outp);
}

// round 2
// speedup vs baseline: 1.5359x; 1.5359x over previous
#include <cuda_runtime.h>
#include <math.h>

// Problem constants (fixed by the reference)
#define NS      65536
#define NBUS    32
#define HD      256
#define TM      16          // samples per CTA
#define THREADS 256

// d_out layout: [out | out_t | physics], each [NS, NBUS] float32, concatenated.

__global__ void __launch_bounds__(THREADS, 3) pinn_kernel(
    const float* __restrict__ t_in,     // [NS,1]
    const float* __restrict__ power,    // [NS,NBUS]
    const float* __restrict__ W0,       // [1,HD]
    const float* __restrict__ b0,       // [HD]
    const float* __restrict__ W1,       // [HD,HD]
    const float* __restrict__ b1,       // [HD]
    const float* __restrict__ W2,       // [HD,NBUS]
    const float* __restrict__ b2,       // [NBUS]
    const float* __restrict__ lam_m,    // [NBUS]
    const float* __restrict__ lam_d,    // [NBUS]
    const float* __restrict__ lam_b,    // [NBUS,NBUS]
    const float* __restrict__ bwi,      // [NBUS]
    float* __restrict__ out_d,          // [NS,NBUS]
    float* __restrict__ out_dt,         // [NS,NBUS]
    float* __restrict__ out_ph)         // [NS,NBUS]
{
    // 3 * 256 * 16 floats = 49152 bytes (exactly the 48KB static limit).
    __shared__ __align__(16) float sh[3 * HD * TM];
    float* sh_h = sh;                 // Phase A/B: [HD][TM]  (k-major, m contiguous)
    float* sh_p = sh + HD * TM;
    float* sh_q = sh + 2 * HD * TM;

    const int tid  = threadIdx.x;
    const int base = blockIdx.x * TM;

    // ---------------- Phase A: layer 0 + its t-derivatives -------------------
    // x = 0.1*t - 1 ; dx/dt = 0.1 ; d2x/dt2 = 0
    #pragma unroll
    for (int idx = tid; idx < HD * TM; idx += THREADS) {
        const int k = idx >> 4;
        const int m = idx & (TM - 1);
        const float t = __ldg(&t_in[base + m]);
        const float x = fmaf(t, 0.1f, -1.0f);
        const float w = __ldg(&W0[k]);
        const float z = fmaf(x, w, __ldg(&b0[k]));
        const float h = tanhf(z);
        const float u = 1.0f - h * h;
        const float d = 0.1f * w;
        sh_h[idx] = h;
        sh_p[idx] = u * d;
        sh_q[idx] = -2.0f * h * u * d * d;
    }
    __syncthreads();

    // ---------------- Phase B: fused 3-stream GEMM with W1 --------------------
    // Thread owns 4 consecutive W1 columns (cg) x 4 samples (mg).
    // Per k: 3 LDS.128 + 1 LDG.128 feed 48 FFMA.
    const int cg = tid & 63;          // column group: cols j0..j0+3
    const int mg = tid >> 6;          // sample group: samples mg*4..mg*4+3
    const int j0 = cg << 2;

    float a0[4][4], a1[4][4], a2[4][4];   // [m][c]
    {
        const float4 bv = __ldg((const float4*)(b1 + j0));
        #pragma unroll
        for (int m = 0; m < 4; m++) {
            a0[m][0] = bv.x; a0[m][1] = bv.y; a0[m][2] = bv.z; a0[m][3] = bv.w;
            #pragma unroll
            for (int c = 0; c < 4; c++) { a1[m][c] = 0.0f; a2[m][c] = 0.0f; }
        }
    }

    {
        const float4* h4 = (const float4*)sh_h;   // index k*4 + mg
        const float4* p4 = (const float4*)sh_p;
        const float4* q4 = (const float4*)sh_q;
        const float*  w1p = W1 + j0;

        float4 wv = __ldg((const float4*)w1p);    // k = 0 prefetch
        for (int k = 0; k < HD; k++) {
            float4 wn;
            if (k + 1 < HD) wn = __ldg((const float4*)(w1p + (k + 1) * HD));
            const float4 hv = h4[k * 4 + mg];
            const float4 pv = p4[k * 4 + mg];
            const float4 qv = q4[k * 4 + mg];
            const float hm[4] = {hv.x, hv.y, hv.z, hv.w};
            const float pm[4] = {pv.x, pv.y, pv.z, pv.w};
            const float qm[4] = {qv.x, qv.y, qv.z, qv.w};
            const float wc[4] = {wv.x, wv.y, wv.z, wv.w};
            #pragma unroll
            for (int m = 0; m < 4; m++) {
                #pragma unroll
                for (int c = 0; c < 4; c++) {
                    a0[m][c] = fmaf(hm[m], wc[c], a0[m][c]);
                    a1[m][c] = fmaf(pm[m], wc[c], a1[m][c]);
                    a2[m][c] = fmaf(qm[m], wc[c], a2[m][c]);
                }
            }
            wv = wn;
        }
    }
    __syncthreads();   // all reads of sh_h/p/q done before relayout

    // ---------------- Phase C: layer-1 tanh chain, write [m][j] layout --------
    // g = tanh(z); g' = (1-g^2) z'; g'' = (1-g^2)(z'' - 2 g z'^2)
    float* sh_g   = sh;               // [TM][HD]
    float* sh_gp  = sh + TM * HD;
    float* sh_gpp = sh + 2 * TM * HD;
    #pragma unroll
    for (int m = 0; m < 4; m++) {
        const int row = (mg << 2) + m;
        float g[4], gp[4], gpp[4];
        #pragma unroll
        for (int c = 0; c < 4; c++) {
            const float gg = tanhf(a0[m][c]);
            const float u  = 1.0f - gg * gg;
            const float zp = a1[m][c];
            g[c]   = gg;
            gp[c]  = u * zp;
            gpp[c] = u * (a2[m][c] - 2.0f * gg * zp * zp);
        }
        *(float4*)(sh_g   + row * HD + j0) = make_float4(g[0], g[1], g[2], g[3]);
        *(float4*)(sh_gp  + row * HD + j0) = make_float4(gp[0], gp[1], gp[2], gp[3]);
        *(float4*)(sh_gpp + row * HD + j0) = make_float4(gpp[0], gpp[1], gpp[2], gpp[3]);
    }
    __syncthreads();

    // ---------------- Phase D: 256 -> 32 projection ---------------------------
    // Thread: bus i = tid%32 (coalesced), samples m = mq and mq+8.
    // Smem loads are warp-wide broadcasts of float4.
    const int i  = tid & 31;
    const int mq = tid >> 5;
    float o[2], op[2], opp[2];
    {
        const float bb = __ldg(&b2[i]);
        o[0] = bb; o[1] = bb;
        op[0] = 0.0f; op[1] = 0.0f;
        opp[0] = 0.0f; opp[1] = 0.0f;
    }
    {
        const float* g0r = sh_g   + mq * HD;
        const float* g1r = sh_g   + (mq + 8) * HD;
        const float* p0r = sh_gp  + mq * HD;
        const float* p1r = sh_gp  + (mq + 8) * HD;
        const float* q0r = sh_gpp + mq * HD;
        const float* q1r = sh_gpp + (mq + 8) * HD;
        for (int j = 0; j < HD; j += 4) {
            const float4 g0 = *(const float4*)(g0r + j);
            const float4 g1 = *(const float4*)(g1r + j);
            const float4 p0 = *(const float4*)(p0r + j);
            const float4 p1 = *(const float4*)(p1r + j);
            const float4 q0 = *(const float4*)(q0r + j);
            const float4 q1 = *(const float4*)(q1r + j);
            const float ga[2][4] = {{g0.x,g0.y,g0.z,g0.w},{g1.x,g1.y,g1.z,g1.w}};
            const float pa[2][4] = {{p0.x,p0.y,p0.z,p0.w},{p1.x,p1.y,p1.z,p1.w}};
            const float qa[2][4] = {{q0.x,q0.y,q0.z,q0.w},{q1.x,q1.y,q1.z,q1.w}};
            float w2[4];
            #pragma unroll
            for (int c = 0; c < 4; c++) w2[c] = __ldg(&W2[(j + c) * NBUS + i]);
            #pragma unroll
            for (int s = 0; s < 2; s++) {
                #pragma unroll
                for (int c = 0; c < 4; c++) {
                    o[s]   = fmaf(ga[s][c], w2[c], o[s]);
                    op[s]  = fmaf(pa[s][c], w2[c], op[s]);
                    opp[s] = fmaf(qa[s][c], w2[c], opp[s]);
                }
            }
        }
    }
    __syncthreads();   // done reading g/g'/g'' ; reuse smem for sin/cos

    // ---------------- Phase E: coupling + physics -----------------------------
    // sum_j B[i][j] sin(d_i - d_j) = s_i*(B@c)_i - c_i*(B@s)_i
    float* sh_s = sh;                 // [TM][NBUS]
    float* sh_c = sh + TM * NBUS;     // [TM][NBUS]
    float sv[2], cv[2];
    #pragma unroll
    for (int s = 0; s < 2; s++) {
        const int m = mq + 8 * s;
        sincosf(o[s], &sv[s], &cv[s]);
        sh_s[m * NBUS + i] = sv[s];
        sh_c[m * NBUS + i] = cv[s];
    }
    __syncthreads();

    const float lm = __ldg(&lam_m[i]) * __ldg(&bwi[i]);
    const float ld = __ldg(&lam_d[i]);
    #pragma unroll
    for (int s = 0; s < 2; s++) {
        const int m = mq + 8 * s;
        float accC = 0.0f, accS = 0.0f;
        #pragma unroll
        for (int j = 0; j < NBUS; j++) {
            const float bij = __ldg(&lam_b[i * NBUS + j]);
            accC = fmaf(bij, sh_c[m * NBUS + j], accC);
            accS = fmaf(bij, sh_s[m * NBUS + j], accS);
        }
        const float conn = sv[s] * accC - cv[s] * accS;
        const int gi = (base + m) * NBUS + i;
        const float ph = fmaf(lm, opp[s], fmaf(ld, op[s], conn - __ldg(&power[gi])));
        out_d[gi]  = o[s];
        out_dt[gi] = op[s];
        out_ph[gi] = ph;
    }
}

extern "C" void kernel_launch(void* const* d_in, const int* in_sizes, int n_in,
                              void* d_out, int out_size) {
    const float* t_in  = (const float*)d_in[0];
    const float* power = (const float*)d_in[1];
    const float* W0    = (const float*)d_in[2];
    const float* b0    = (const float*)d_in[3];
    const float* W1    = (const float*)d_in[4];
    const float* b1    = (const float*)d_in[5];
    const float* W2    = (const float*)d_in[6];
    const float* b2    = (const float*)d_in[7];
    const float* lam_m = (const float*)d_in[8];
    const float* lam_d = (const float*)d_in[9];
    const float* lam_b = (const float*)d_in[10];
    const float* bwi   = (const float*)d_in[11];

    float* out  = (float*)d_out;
    float* outt = out  + (size_t)NS * NBUS;
    float* outp = outt + (size_t)NS * NBUS;

    pinn_kernel<<<NS / TM, THREADS>>>(t_in, power, W0, b0, W1, b1, W2, b2,
                                      lam_m, lam_d, lam_b, bwi,
                                      out, outt, outp);
}

// round 4
// speedup vs baseline: 3.0007x; 1.9538x over previous
#include <cuda_runtime.h>
#include <cuda_bf16.h>
#include <math.h>
#include <stdint.h>

#define NS      65536
#define NBUS    32
#define HD      256
#define MT      64            // samples per CTA
#define NCTA    (NS / MT)
#define THREADS 256
#define NCH     8             // n-chunks of 32 over HD=256

// ---- smem map (dynamic, 229376 B total) ----
// A tiles: 3 streams (h,p,q) x hi/lo, each [64 m][256 k] bf16 = 32768 B
#define A_T(s,hl) (((s)*2+(hl))*32768)
#define B1_T(hl)  (196608 + (hl)*16384)   // W1^T chunk [32 n][256 k] bf16 hi/lo
#define SMEM_TOTAL 229376
// final-phase aliases (A region is dead by then)
#define O_OFF   0             // out      [64][32] f32
#define OT_OFF  8192          // out_t    [64][32] f32
#define OTT_OFF 16384         // out_tt   [64][32] f32
#define SCS_OFF 24576         // sin      [64][33] f32
#define SCC_OFF 33024         // cos      [64][33] f32

static __device__ __forceinline__ uint32_t s2u(const void* p) {
    uint32_t a;
    asm("{ .reg .u64 t; cvta.to.shared.u64 t, %1; cvt.u32.u64 %0, t; }" : "=r"(a) : "l"(p));
    return a;
}
static __device__ __forceinline__ uint32_t pk(float a, float b) {
    __nv_bfloat162 t = __floats2bfloat162_rn(a, b);
    return *reinterpret_cast<uint32_t*>(&t);
}
static __device__ __forceinline__ float bhi(float v) {
    return __bfloat162float(__float2bfloat16(v));
}
static __device__ __forceinline__ void ldsm4(uint32_t* r, uint32_t a) {
    asm volatile("ldmatrix.sync.aligned.m8n8.x4.shared.b16 {%0,%1,%2,%3}, [%4];"
                 : "=r"(r[0]), "=r"(r[1]), "=r"(r[2]), "=r"(r[3]) : "r"(a));
}
static __device__ __forceinline__ void mma16816(float* d, const uint32_t* a,
                                                uint32_t b0, uint32_t b1) {
    asm volatile(
        "mma.sync.aligned.m16n8k16.row.col.f32.bf16.bf16.f32 "
        "{%0,%1,%2,%3}, {%4,%5,%6,%7}, {%8,%9}, {%0,%1,%2,%3};"
        : "+f"(d[0]), "+f"(d[1]), "+f"(d[2]), "+f"(d[3])
        : "r"(a[0]), "r"(a[1]), "r"(a[2]), "r"(a[3]), "r"(b0), "r"(b1));
}

__global__ void __launch_bounds__(THREADS, 1) pinn_hmma_kernel(
    const float* __restrict__ t_in, const float* __restrict__ power,
    const float* __restrict__ W0, const float* __restrict__ b0,
    const float* __restrict__ W1, const float* __restrict__ b1,
    const float* __restrict__ W2, const float* __restrict__ b2,
    const float* __restrict__ lam_m, const float* __restrict__ lam_d,
    const float* __restrict__ lam_b, const float* __restrict__ bwi,
    float* __restrict__ out_d, float* __restrict__ out_dt, float* __restrict__ out_ph)
{
    extern __shared__ __align__(1024) char smc[];
    const uint32_t sb = s2u(smc);

    const int tid   = threadIdx.x;
    const int lane  = tid & 31;
    const int wid   = tid >> 5;
    const int warpM = wid & 3;     // m-tile: rows warpM*16 .. +15
    const int warpN = wid >> 2;    // n-tile within 32-chunk: cols warpN*16 .. +15
    const int base  = blockIdx.x * MT;

    // ============ Phase A: generate h/p/q split tiles (once per CTA) ============
    // element (m,k): byte off = m*512 + (((k>>3)^(m&7))<<4) + (k&7)*2
    {
        const int gm  = tid >> 2;            // 0..63
        const int gk0 = (tid & 3) * 64;      // k range start
        const float t = __ldg(&t_in[base + gm]);
        const float x = fmaf(t, 0.1f, -1.0f);
        #pragma unroll 4
        for (int kk = 0; kk < 64; kk += 2) {
            const int k = gk0 + kk;
            float hv[2], pv[2], qv[2];
            #pragma unroll
            for (int e = 0; e < 2; e++) {
                const float w = __ldg(&W0[k + e]);
                const float d = 0.1f * w;
                const float z = fmaf(x, w, __ldg(&b0[k + e]));
                const float h = tanhf(z);
                const float u = 1.0f - h * h;
                hv[e] = h; pv[e] = u * d; qv[e] = -2.0f * h * u * d * d;
            }
            const uint32_t off = (uint32_t)(gm * 512 + ((((k >> 3) ^ (gm & 7))) << 4) + (k & 7) * 2);
            float h0 = bhi(hv[0]), h1 = bhi(hv[1]);
            *(uint32_t*)(smc + A_T(0,0) + off) = pk(h0, h1);
            *(uint32_t*)(smc + A_T(0,1) + off) = pk(hv[0] - h0, hv[1] - h1);
            h0 = bhi(pv[0]); h1 = bhi(pv[1]);
            *(uint32_t*)(smc + A_T(1,0) + off) = pk(h0, h1);
            *(uint32_t*)(smc + A_T(1,1) + off) = pk(pv[0] - h0, pv[1] - h1);
            h0 = bhi(qv[0]); h1 = bhi(qv[1]);
            *(uint32_t*)(smc + A_T(2,0) + off) = pk(h0, h1);
            *(uint32_t*)(smc + A_T(2,1) + off) = pk(qv[0] - h0, qv[1] - h1);
        }
    }

    // per-thread ldmatrix address components (canonical x4: lanes 0-15 rows, 16-31 k-half)
    const int l16 = lane & 15;
    const int csel = lane >> 4;
    const uint32_t xr   = (uint32_t)(l16 & 7);
    const uint32_t rowA = (uint32_t)((warpM * 16 + l16) * 512);
    const uint32_t rowB = (uint32_t)((warpN * 16 + l16) * 512);
    const int q  = lane & 3;       // C/A-frag col-pair & B-frag k-pair
    const int br = lane >> 2;      // C/A-frag row & B-frag n

    // layer-2 accumulators: out/out_t/out_tt [16m x 32bus] per warp (partial over k2)
    float acc2[3][4][4];
    #pragma unroll
    for (int s = 0; s < 3; s++)
        #pragma unroll
        for (int nb = 0; nb < 4; nb++)
            #pragma unroll
            for (int e = 0; e < 4; e++) acc2[s][nb][e] = 0.0f;

    // ============ main loop over 8 n-chunks of 32 columns ============
    for (int c = 0; c < NCH; c++) {
        __syncthreads();   // prior chunk's B1 reads (and phase-A writes) complete

        // ---- load W1^T chunk: [32 n][256 k] bf16 hi/lo ----
        {
            const int n = tid & 31;
            #pragma unroll 4
            for (int i = 0; i < 16; i++) {
                const int kp = (tid >> 5) + i * 8;
                const int k  = kp * 2;
                const float v0 = __ldg(&W1[(size_t)k * HD + c * 32 + n]);
                const float v1 = __ldg(&W1[(size_t)(k + 1) * HD + c * 32 + n]);
                const float h0 = bhi(v0), h1 = bhi(v1);
                const uint32_t off = (uint32_t)(n * 512 + ((((k >> 3) ^ (n & 7))) << 4) + (k & 7) * 2);
                *(uint32_t*)(smc + B1_T(0) + off) = pk(h0, h1);
                *(uint32_t*)(smc + B1_T(1) + off) = pk(v0 - h0, v1 - h1);
            }
        }
        __syncthreads();

        // ---- layer-1: z/zp/zq [16m x 16n] per warp, K = 256 ----
        float acc[3][2][4];
        #pragma unroll
        for (int s = 0; s < 3; s++)
            #pragma unroll
            for (int t = 0; t < 2; t++)
                #pragma unroll
                for (int e = 0; e < 4; e++) acc[s][t][e] = 0.0f;

        #pragma unroll 4
        for (int kt = 0; kt < 16; kt++) {
            const uint32_t co = (uint32_t)((((kt * 2 + csel)) ^ xr) << 4);
            uint32_t ah[3][4], al[3][4], bh[4], bl[4];
            #pragma unroll
            for (int s = 0; s < 3; s++) {
                ldsm4(ah[s], sb + A_T(s,0) + rowA + co);
                ldsm4(al[s], sb + A_T(s,1) + rowA + co);
            }
            ldsm4(bh, sb + B1_T(0) + rowB + co);
            ldsm4(bl, sb + B1_T(1) + rowB + co);
            #pragma unroll
            for (int s = 0; s < 3; s++) {
                #pragma unroll
                for (int t = 0; t < 2; t++) {
                    mma16816(acc[s][t], ah[s], bh[t], bh[t + 2]);
                    mma16816(acc[s][t], al[s], bh[t], bh[t + 2]);
                    mma16816(acc[s][t], ah[s], bl[t], bl[t + 2]);
                }
            }
        }

        // ---- in-register epilogue: bias + tanh chain -> G fragments ----
        const int jg = c * 32 + warpN * 16;   // this warp's 16 j-columns (k2 tile)
        float vg[2][4], vp[2][4], vq[2][4];
        #pragma unroll
        for (int t = 0; t < 2; t++) {
            const float b1a = __ldg(&b1[jg + t * 8 + 2 * q]);
            const float b1b = __ldg(&b1[jg + t * 8 + 2 * q + 1]);
            #pragma unroll
            for (int e = 0; e < 4; e++) {
                const float zh = acc[0][t][e] + ((e & 1) ? b1b : b1a);
                const float zp = acc[1][t][e];
                const float zq = acc[2][t][e];
                const float g  = tanhf(zh);
                const float u  = 1.0f - g * g;
                vg[t][e] = g;
                vp[t][e] = u * zp;
                vq[t][e] = u * fmaf(-2.0f * g * zp, zp, zq);
            }
        }

        // ---- layer-2: C2 += G(k2=16) @ W2 ; A-frags direct from C-frags ----
        uint32_t w2h[4][2], w2l[4][2];
        #pragma unroll
        for (int nb = 0; nb < 4; nb++) {
            const int bus = nb * 8 + br;
            const float v0 = __ldg(&W2[(size_t)(jg + 2 * q)     * NBUS + bus]);
            const float v1 = __ldg(&W2[(size_t)(jg + 2 * q + 1) * NBUS + bus]);
            const float v2 = __ldg(&W2[(size_t)(jg + 2 * q + 8) * NBUS + bus]);
            const float v3 = __ldg(&W2[(size_t)(jg + 2 * q + 9) * NBUS + bus]);
            const float h0 = bhi(v0), h1 = bhi(v1), h2 = bhi(v2), h3 = bhi(v3);
            w2h[nb][0] = pk(h0, h1);          w2h[nb][1] = pk(h2, h3);
            w2l[nb][0] = pk(v0 - h0, v1 - h1); w2l[nb][1] = pk(v2 - h2, v3 - h3);
        }
        #pragma unroll
        for (int s = 0; s < 3; s++) {
            const float (*v)[4] = (s == 0) ? vg : (s == 1) ? vp : vq;
            uint32_t a2h[4], a2l[4];
            // a0={(r,k01) t0 c01}, a1={t0 c23}, a2={t1 c01}, a3={t1 c23}
            float x0 = bhi(v[0][0]), x1 = bhi(v[0][1]);
            a2h[0] = pk(x0, x1); a2l[0] = pk(v[0][0] - x0, v[0][1] - x1);
            x0 = bhi(v[0][2]); x1 = bhi(v[0][3]);
            a2h[1] = pk(x0, x1); a2l[1] = pk(v[0][2] - x0, v[0][3] - x1);
            x0 = bhi(v[1][0]); x1 = bhi(v[1][1]);
            a2h[2] = pk(x0, x1); a2l[2] = pk(v[1][0] - x0, v[1][1] - x1);
            x0 = bhi(v[1][2]); x1 = bhi(v[1][3]);
            a2h[3] = pk(x0, x1); a2l[3] = pk(v[1][2] - x0, v[1][3] - x1);
            #pragma unroll
            for (int nb = 0; nb < 4; nb++) {
                mma16816(acc2[s][nb], a2h, w2h[nb][0], w2h[nb][1]);
                mma16816(acc2[s][nb], a2l, w2h[nb][0], w2h[nb][1]);
                mma16816(acc2[s][nb], a2h, w2l[nb][0], w2l[nb][1]);
            }
        }
    }

    // ============ cross-warp k2 reduction + physics ============
    __syncthreads();   // all A/B1 smem reads done -> safe to alias
    float* f_o   = (float*)(smc + O_OFF);
    float* f_ot  = (float*)(smc + OT_OFF);
    float* f_ott = (float*)(smc + OTT_OFF);
    float* scs   = (float*)(smc + SCS_OFF);
    float* scc   = (float*)(smc + SCC_OFF);

    if (warpN == 0) {
        #pragma unroll
        for (int s = 0; s < 3; s++) {
            float* dst = (s == 0) ? f_o : (s == 1) ? f_ot : f_ott;
            #pragma unroll
            for (int nb = 0; nb < 4; nb++)
                #pragma unroll
                for (int e = 0; e < 4; e++) {
                    const int row = warpM * 16 + br + ((e >> 1) << 3);
                    const int bus = nb * 8 + 2 * q + (e & 1);
                    dst[row * NBUS + bus] = acc2[s][nb][e];
                }
        }
    }
    __syncthreads();
    if (warpN == 1) {
        #pragma unroll
        for (int s = 0; s < 3; s++) {
            float* dst = (s == 0) ? f_o : (s == 1) ? f_ot : f_ott;
            #pragma unroll
            for (int nb = 0; nb < 4; nb++)
                #pragma unroll
                for (int e = 0; e < 4; e++) {
                    const int row = warpM * 16 + br + ((e >> 1) << 3);
                    const int bus = nb * 8 + 2 * q + (e & 1);
                    float v = dst[row * NBUS + bus] + acc2[s][nb][e];
                    if (s == 0) v += __ldg(&b2[bus]);
                    dst[row * NBUS + bus] = v;
                }
        }
    }
    __syncthreads();

    // sin/cos tables
    #pragma unroll
    for (int i = 0; i < 8; i++) {
        const int cell = tid * 8 + i;
        const int m = cell >> 5, bus = cell & 31;
        float sv, cv;
        sincosf(f_o[cell], &sv, &cv);
        scs[m * 33 + bus] = sv;
        scc[m * 33 + bus] = cv;
    }
    __syncthreads();

    // physics: thread -> sample pm, buses pb..pb+7
    const int pm = tid >> 2;
    const int pb = (tid & 3) * 8;
    #pragma unroll
    for (int g4 = 0; g4 < 2; g4++) {
        float4 vo, vt, vp4;
        float* po = &vo.x; float* pt = &vt.x; float* pp = &vp4.x;
        const float4 pw = __ldg((const float4*)(power + (size_t)(base + pm) * NBUS + pb + g4 * 4));
        const float* ppw = &pw.x;
        #pragma unroll
        for (int e = 0; e < 4; e++) {
            const int bus = pb + g4 * 4 + e;
            const float o   = f_o  [pm * NBUS + bus];
            const float ot  = f_ot [pm * NBUS + bus];
            const float ott = f_ott[pm * NBUS + bus];
            float accC = 0.0f, accS = 0.0f;
            #pragma unroll
            for (int j = 0; j < NBUS; j++) {
                const float bl2 = __ldg(&lam_b[bus * NBUS + j]);
                accC = fmaf(bl2, scc[pm * 33 + j], accC);
                accS = fmaf(bl2, scs[pm * 33 + j], accS);
            }
            const float conn = scs[pm * 33 + bus] * accC - scc[pm * 33 + bus] * accS;
            const float lm = __ldg(&lam_m[bus]) * __ldg(&bwi[bus]);
            const float ld = __ldg(&lam_d[bus]);
            po[e] = o;
            pt[e] = ot;
            pp[e] = fmaf(lm, ott, fmaf(ld, ot, conn - ppw[e]));
        }
        const size_t gi = (size_t)(base + pm) * NBUS + pb + g4 * 4;
        *(float4*)(out_d  + gi) = vo;
        *(float4*)(out_dt + gi) = vt;
        *(float4*)(out_ph + gi) = vp4;
    }
}

extern "C" void kernel_launch(void* const* d_in, const int* in_sizes, int n_in,
                              void* d_out, int out_size) {
    const float* t_in  = (const float*)d_in[0];
    const float* power = (const float*)d_in[1];
    const float* W0    = (const float*)d_in[2];
    const float* b0    = (const float*)d_in[3];
    const float* W1    = (const float*)d_in[4];
    const float* b1    = (const float*)d_in[5];
    const float* W2    = (const float*)d_in[6];
    const float* b2    = (const float*)d_in[7];
    const float* lam_m = (const float*)d_in[8];
    const float* lam_d = (const float*)d_in[9];
    const float* lam_b = (const float*)d_in[10];
    const float* bwi   = (const float*)d_in[11];

    float* out  = (float*)d_out;
    float* outt = out  + (size_t)NS * NBUS;
    float* outp = outt + (size_t)NS * NBUS;

    cudaFuncSetAttribute(pinn_hmma_kernel, cudaFuncAttributeMaxDynamicSharedMemorySize, SMEM_TOTAL);
    pinn_hmma_kernel<<<NCTA, THREADS, SMEM_TOTAL>>>(t_in, power, W0, b0, W1, b1, W2, b2,
                                                    lam_m, lam_d, lam_b, bwi,
                                                    out, outt, outp);
}